// round 1
// baseline (speedup 1.0000x reference)
#include <cuda_runtime.h>
#include <cstdint>
#include <cstddef>

#define T_SEQ   2048
#define D_DIM   256
#define B_BATCH 32
#define H_DIM   1024
#define M_ROWS  (B_BATCH * T_SEQ)          /* 65536 */
#define HALF_OFF ((size_t)M_ROWS * 256)    /* split point in d_out */

// Scratch (static device globals: allocation-free per harness rules)
__device__ float g_ctx[(size_t)M_ROWS * D_DIM];     // 64 MB
__device__ float g_h[(size_t)M_ROWS * H_DIM];       // 256 MB

// ---------------------------------------------------------------------------
// Attention: flash-style fp32, BQ=64 queries, BK=64 keys per tile, D=256.
// Thread layout: 256 threads = 16x16 (tx, ty). Each thread owns
//   queries  i = ty*4 + r   (r = 0..3)
//   S cols   j = tx + 16*jj (jj = 0..3)
//   O cols   d = tx + 16*cc (cc = 0..15)
// ---------------------------------------------------------------------------
#define QP 68     // Qt row pad (Qt is [d][i], 256 x 64)
#define KP 261    // Ks row pad (odd -> conflict-free strided loads in S-phase)
#define PP 68     // Ps row pad (Ps is [j][i])
#define ATTN_SMEM ((256 * QP + 64 * KP + 64 * PP) * 4)

__global__ __launch_bounds__(256, 1)
void attn_kernel(const float* __restrict__ x)
{
    extern __shared__ float sm[];
    float* Qt = sm;                 // [256][QP]
    float* Ks = sm + 256 * QP;      // [64][KP]
    float* Ps = Ks + 64 * KP;       // [64][PP]

    const int qt  = blockIdx.x;     // query tile 0..31
    const int b   = blockIdx.y;     // batch
    const int tid = threadIdx.x;
    const int tx  = tid & 15;
    const int ty  = tid >> 4;
    const float* xb = x + (size_t)b * T_SEQ * D_DIM;
    const int q0 = qt * 64;

    // Load Q tile transposed, pre-scaled by 1/sqrt(D) = 1/16
    for (int idx = tid; idx < 64 * 64; idx += 256) {
        int ii = idx >> 6, d4 = idx & 63;
        float4 v = *(const float4*)(xb + (size_t)(q0 + ii) * D_DIM + d4 * 4);
        Qt[(d4 * 4 + 0) * QP + ii] = v.x * 0.0625f;
        Qt[(d4 * 4 + 1) * QP + ii] = v.y * 0.0625f;
        Qt[(d4 * 4 + 2) * QP + ii] = v.z * 0.0625f;
        Qt[(d4 * 4 + 3) * QP + ii] = v.w * 0.0625f;
    }

    float acc[4][16];
    #pragma unroll
    for (int r = 0; r < 4; r++)
        #pragma unroll
        for (int c = 0; c < 16; c++) acc[r][c] = 0.f;
    float mr[4], lr[4];
    #pragma unroll
    for (int r = 0; r < 4; r++) { mr[r] = -1e30f; lr[r] = 0.f; }

    for (int kt = 0; kt <= qt; ++kt) {
        __syncthreads();   // Qt visible (first iter) / prev O-phase done
        // Load K tile (natural [j][d], padded rows)
        for (int idx = tid; idx < 64 * 64; idx += 256) {
            int jj = idx >> 6, d4 = idx & 63;
            float4 v = *(const float4*)(xb + (size_t)(kt * 64 + jj) * D_DIM + d4 * 4);
            float* kp = Ks + jj * KP + d4 * 4;
            kp[0] = v.x; kp[1] = v.y; kp[2] = v.z; kp[3] = v.w;
        }
        __syncthreads();

        // S = Q K^T  (4x4 microtile per thread)
        float s[4][4];
        #pragma unroll
        for (int r = 0; r < 4; r++)
            #pragma unroll
            for (int jj = 0; jj < 4; jj++) s[r][jj] = 0.f;

        #pragma unroll 4
        for (int d = 0; d < 256; ++d) {
            float4 q = *(const float4*)&Qt[d * QP + ty * 4];
            #pragma unroll
            for (int jj = 0; jj < 4; jj++) {
                float kv = Ks[(tx + 16 * jj) * KP + d];
                s[0][jj] += q.x * kv;
                s[1][jj] += q.y * kv;
                s[2][jj] += q.z * kv;
                s[3][jj] += q.w * kv;
            }
        }

        // Strictly-causal mask on the diagonal tile: key j < query i only
        if (kt == qt) {
            #pragma unroll
            for (int r = 0; r < 4; r++)
                #pragma unroll
                for (int jj = 0; jj < 4; jj++)
                    if (tx + 16 * jj >= ty * 4 + r) s[r][jj] = -1e30f;
        }

        // Online softmax update + write P (transposed [j][i])
        #pragma unroll
        for (int r = 0; r < 4; r++) {
            float rm = fmaxf(fmaxf(s[r][0], s[r][1]), fmaxf(s[r][2], s[r][3]));
            rm = fmaxf(rm, __shfl_xor_sync(0xffffffffu, rm, 1, 16));
            rm = fmaxf(rm, __shfl_xor_sync(0xffffffffu, rm, 2, 16));
            rm = fmaxf(rm, __shfl_xor_sync(0xffffffffu, rm, 4, 16));
            rm = fmaxf(rm, __shfl_xor_sync(0xffffffffu, rm, 8, 16));
            float mn = fmaxf(mr[r], rm);
            float sc = __expf(mr[r] - mn);
            mr[r] = mn;
            float ps0 = __expf(s[r][0] - mn);
            float ps1 = __expf(s[r][1] - mn);
            float ps2 = __expf(s[r][2] - mn);
            float ps3 = __expf(s[r][3] - mn);
            float rs = ps0 + ps1 + ps2 + ps3;
            rs += __shfl_xor_sync(0xffffffffu, rs, 1, 16);
            rs += __shfl_xor_sync(0xffffffffu, rs, 2, 16);
            rs += __shfl_xor_sync(0xffffffffu, rs, 4, 16);
            rs += __shfl_xor_sync(0xffffffffu, rs, 8, 16);
            lr[r] = lr[r] * sc + rs;
            #pragma unroll
            for (int cc = 0; cc < 16; cc++) acc[r][cc] *= sc;
            Ps[(tx + 16 * 0) * PP + ty * 4 + r] = ps0;
            Ps[(tx + 16 * 1) * PP + ty * 4 + r] = ps1;
            Ps[(tx + 16 * 2) * PP + ty * 4 + r] = ps2;
            Ps[(tx + 16 * 3) * PP + ty * 4 + r] = ps3;
        }
        __syncthreads();

        // O += P K   (rows i = ty*4+r, cols d = tx + 16*cc)
        #pragma unroll 2
        for (int j = 0; j < 64; ++j) {
            float4 p = *(const float4*)&Ps[j * PP + ty * 4];
            const float* kr = Ks + j * KP + tx;
            #pragma unroll
            for (int cc = 0; cc < 16; cc++) {
                float kv = kr[cc * 16];
                acc[0][cc] += p.x * kv;
                acc[1][cc] += p.y * kv;
                acc[2][cc] += p.z * kv;
                acc[3][cc] += p.w * kv;
            }
        }
    }

    // Final normalize + store ctx; t=0 row forced to zero (matches reference)
    #pragma unroll
    for (int r = 0; r < 4; r++) {
        int ig = q0 + ty * 4 + r;
        float inv = (ig > 0 && lr[r] > 0.f) ? (1.0f / lr[r]) : 0.f;
        float* crow = g_ctx + ((size_t)b * T_SEQ + ig) * D_DIM;
        #pragma unroll
        for (int cc = 0; cc < 16; cc++)
            crow[tx + 16 * cc] = acc[r][cc] * inv;
    }
}

// ---------------------------------------------------------------------------
// fc1: h = relu([x | ctx] @ W1 + b1)   M=65536, K=512, N=1024
// 128x128 block tile, 16-deep k tile, 8x8 per-thread microtile,
// register prefetch of the next k-tile overlapped with compute.
// ---------------------------------------------------------------------------
__global__ __launch_bounds__(256, 2)
void fc1_kernel(const float* __restrict__ x,
                const float* __restrict__ W1,
                const float* __restrict__ b1)
{
    __shared__ float As[16][132];
    __shared__ float Bs[16][132];
    const int bm = blockIdx.y * 128, bn = blockIdx.x * 128;
    const int tid = threadIdx.x, tx = tid & 15, ty = tid >> 4;

    float acc[8][8];
    #pragma unroll
    for (int i = 0; i < 8; i++)
        #pragma unroll
        for (int j = 0; j < 8; j++) acc[i][j] = 0.f;

    float4 pa[2], pb[2];

    auto loadA = [&](int k0) {
        #pragma unroll
        for (int r = 0; r < 2; r++) {
            int idx = tid + r * 256;
            int m = idx >> 2, kq = idx & 3;
            const float* base = (k0 < 256) ? (x + k0) : (g_ctx + (k0 - 256));
            pa[r] = *(const float4*)(base + (size_t)(bm + m) * 256 + kq * 4);
        }
    };
    auto loadB = [&](int k0) {
        #pragma unroll
        for (int r = 0; r < 2; r++) {
            int idx = tid + r * 256;
            int kk = idx >> 5, n4 = idx & 31;
            pb[r] = *(const float4*)(W1 + (size_t)(k0 + kk) * 1024 + bn + n4 * 4);
        }
    };
    auto storeS = [&]() {
        #pragma unroll
        for (int r = 0; r < 2; r++) {
            int idx = tid + r * 256;
            int m = idx >> 2, kq = idx & 3;
            As[kq * 4 + 0][m] = pa[r].x;
            As[kq * 4 + 1][m] = pa[r].y;
            As[kq * 4 + 2][m] = pa[r].z;
            As[kq * 4 + 3][m] = pa[r].w;
        }
        #pragma unroll
        for (int r = 0; r < 2; r++) {
            int idx = tid + r * 256;
            int kk = idx >> 5, n4 = idx & 31;
            *(float4*)&Bs[kk][n4 * 4] = pb[r];
        }
    };

    loadA(0); loadB(0); storeS();
    int k0 = 0;
    while (true) {
        __syncthreads();
        int kn = k0 + 16;
        bool more = kn < 512;
        if (more) { loadA(kn); loadB(kn); }
        #pragma unroll
        for (int kk = 0; kk < 16; kk++) {
            float a[8], bb[8];
            *(float4*)&a[0]  = *(const float4*)&As[kk][ty * 8];
            *(float4*)&a[4]  = *(const float4*)&As[kk][ty * 8 + 4];
            *(float4*)&bb[0] = *(const float4*)&Bs[kk][tx * 8];
            *(float4*)&bb[4] = *(const float4*)&Bs[kk][tx * 8 + 4];
            #pragma unroll
            for (int i = 0; i < 8; i++)
                #pragma unroll
                for (int j = 0; j < 8; j++) acc[i][j] += a[i] * bb[j];
        }
        if (!more) break;
        __syncthreads();
        storeS();
        k0 = kn;
    }

    #pragma unroll
    for (int i = 0; i < 8; i++) {
        size_t m = (size_t)(bm + ty * 8 + i);
        float* hr = g_h + m * 1024 + bn + tx * 8;
        #pragma unroll
        for (int j = 0; j < 8; j++) {
            float v = acc[i][j] + b1[bn + tx * 8 + j];
            hr[j] = fmaxf(v, 0.f);
        }
    }
}

// ---------------------------------------------------------------------------
// fc2: out = h @ W2 + b2   M=65536, K=1024, N=512; split-halves store:
//   cols [0,256)   -> d_out[          m*256 + n      ]
//   cols [256,512) -> d_out[HALF_OFF + m*256 + n-256 ]
// ---------------------------------------------------------------------------
__global__ __launch_bounds__(256, 2)
void fc2_kernel(const float* __restrict__ W2,
                const float* __restrict__ b2,
                float* __restrict__ out)
{
    __shared__ float As[16][132];
    __shared__ float Bs[16][132];
    const int bm = blockIdx.y * 128, bn = blockIdx.x * 128;
    const int tid = threadIdx.x, tx = tid & 15, ty = tid >> 4;

    float acc[8][8];
    #pragma unroll
    for (int i = 0; i < 8; i++)
        #pragma unroll
        for (int j = 0; j < 8; j++) acc[i][j] = 0.f;

    float4 pa[2], pb[2];

    auto loadA = [&](int k0) {
        #pragma unroll
        for (int r = 0; r < 2; r++) {
            int idx = tid + r * 256;
            int m = idx >> 2, kq = idx & 3;
            pa[r] = *(const float4*)(g_h + (size_t)(bm + m) * 1024 + k0 + kq * 4);
        }
    };
    auto loadB = [&](int k0) {
        #pragma unroll
        for (int r = 0; r < 2; r++) {
            int idx = tid + r * 256;
            int kk = idx >> 5, n4 = idx & 31;
            pb[r] = *(const float4*)(W2 + (size_t)(k0 + kk) * 512 + bn + n4 * 4);
        }
    };
    auto storeS = [&]() {
        #pragma unroll
        for (int r = 0; r < 2; r++) {
            int idx = tid + r * 256;
            int m = idx >> 2, kq = idx & 3;
            As[kq * 4 + 0][m] = pa[r].x;
            As[kq * 4 + 1][m] = pa[r].y;
            As[kq * 4 + 2][m] = pa[r].z;
            As[kq * 4 + 3][m] = pa[r].w;
        }
        #pragma unroll
        for (int r = 0; r < 2; r++) {
            int idx = tid + r * 256;
            int kk = idx >> 5, n4 = idx & 31;
            *(float4*)&Bs[kk][n4 * 4] = pb[r];
        }
    };

    loadA(0); loadB(0); storeS();
    int k0 = 0;
    while (true) {
        __syncthreads();
        int kn = k0 + 16;
        bool more = kn < 1024;
        if (more) { loadA(kn); loadB(kn); }
        #pragma unroll
        for (int kk = 0; kk < 16; kk++) {
            float a[8], bb[8];
            *(float4*)&a[0]  = *(const float4*)&As[kk][ty * 8];
            *(float4*)&a[4]  = *(const float4*)&As[kk][ty * 8 + 4];
            *(float4*)&bb[0] = *(const float4*)&Bs[kk][tx * 8];
            *(float4*)&bb[4] = *(const float4*)&Bs[kk][tx * 8 + 4];
            #pragma unroll
            for (int i = 0; i < 8; i++)
                #pragma unroll
                for (int j = 0; j < 8; j++) acc[i][j] += a[i] * bb[j];
        }
        if (!more) break;
        __syncthreads();
        storeS();
        k0 = kn;
    }

    #pragma unroll
    for (int i = 0; i < 8; i++) {
        size_t m = (size_t)(bm + ty * 8 + i);
        int n0 = bn + tx * 8;   // all 8 cols of a thread are in the same half
        float* orow = (n0 < 256) ? (out + m * 256 + n0)
                                 : (out + HALF_OFF + m * 256 + (n0 - 256));
        #pragma unroll
        for (int j = 0; j < 8; j++)
            orow[j] = acc[i][j] + b2[n0 + j];
    }
}

// ---------------------------------------------------------------------------
extern "C" void kernel_launch(void* const* d_in, const int* in_sizes, int n_in,
                              void* d_out, int out_size)
{
    const float* x  = (const float*)d_in[0];
    const float* W1 = (const float*)d_in[1];
    const float* b1 = (const float*)d_in[2];
    const float* W2 = (const float*)d_in[3];
    const float* b2 = (const float*)d_in[4];
    float* out = (float*)d_out;

    cudaFuncSetAttribute(attn_kernel,
                         cudaFuncAttributeMaxDynamicSharedMemorySize, ATTN_SMEM);

    attn_kernel<<<dim3(32, B_BATCH), 256, ATTN_SMEM>>>(x);
    fc1_kernel<<<dim3(8, 512), 256>>>(x, W1, b1);
    fc2_kernel<<<dim3(4, 512), 256>>>(W2, b2, out);
}